// round 15
// baseline (speedup 1.0000x reference)
#include <cuda_runtime.h>
#include <cuda_bf16.h>

// ---------------------------------------------------------------------------
// FastGaussian2D — gaussian-pair packed f32x2, DUAL-STREAM depth-1 pipeline.
//
// R13 post-mortem: depth-2 pipeline REGRESSED (66.0 vs 61.9us): regs 58->84,
// alu 11.3->23.6% — clamped prefetch (ISETP+SEL/iter) + rotation overhead ate
// the latency win. R12 (depth-1) stays the base.
//
// Model: with RF banking (FFMA2 reading 3 distinct reg-pairs -> rt=3), R12's
// iteration costs 43 FMA-pipe cyc -> busiest-SMSP FMA floor ~77k cyc (43us).
// R12 ran 105k cyc: ~28k of exposed MUFU/FMA non-overlap remains.
//
// Fix: TWO independent R12-style streams per chunk, interleaved in one loop:
//   stream A = entries [0, half), stream B = [half, 2*half).
//   body: EX2_A, EX2_B (launch)  ->  e-eval A(g+1), B(g+1)  ->
//         accum A(g), accum B(g)  (single accumulator set, A-then-B order)
// Between EX2(A) and accum(A): ~9 FMA + 4 MUFU + 9 FMA > EX2 burst latency.
// ILP comes from stream independence — NO clamps, NO extra alu vs R12.
// Odd cnt handled by a scalar tail entry. Summation regrouping only.
//
// Scheduling identical to R12: 152 CTAs x 512 thr, slot rotation (w+c)&15
// (exactly 7/6 units per SMSP), 16KB table + 32KB handoff = 48KB static smem.
//
// Prediction: 61.9 -> 48-54us; fma% ~55-62; alu% ~12-15; regs ~70.
// ---------------------------------------------------------------------------

#define NMAX        2048
#define PMAXPAIR    (NMAX / 2)
#define CPAIR       256        // gaussian pairs per chunk (512 gaussians)
#define BLOCK       512
#define NSLOT       16         // warps per block == tile slots per block
#define GRID        152
#define MIN_ALPHA   1e-8f
#define MIN_SCALE   0.1f
#define LOG2E_F     1.4426950408889634f

typedef unsigned long long u64;

// Pair table: per gaussian pair j (g0=2j, g1=2j+1), 4 ulonglong2 at g_tab[4j..]:
//   [0] = { {-px0,-px1} , {-py0,-py1} }
//   [1] = { {a0,a1}     , {b0,b1}     }
//   [2] = { {c00,c01}   , {cr0,cr1}   }
//   [3] = { {cg0,cg1}   , {cb0,cb1}   }
__device__ ulonglong2 g_tab[4 * PMAXPAIR];

// ---------------- packed f32x2 helpers (sm_103a, PTX-only) -----------------
__device__ __forceinline__ u64 pack2(float lo, float hi) {
    u64 r; asm("mov.b64 %0, {%1, %2};" : "=l"(r) : "f"(lo), "f"(hi)); return r;
}
__device__ __forceinline__ void unpack2(u64 v, float& lo, float& hi) {
    asm("mov.b64 {%0, %1}, %2;" : "=f"(lo), "=f"(hi) : "l"(v));
}
__device__ __forceinline__ u64 f2add(u64 a, u64 b) {
    u64 r; asm("add.rn.f32x2 %0, %1, %2;" : "=l"(r) : "l"(a), "l"(b)); return r;
}
__device__ __forceinline__ u64 f2mul(u64 a, u64 b) {
    u64 r; asm("mul.rn.f32x2 %0, %1, %2;" : "=l"(r) : "l"(a), "l"(b)); return r;
}
__device__ __forceinline__ u64 f2fma(u64 a, u64 b, u64 c) {
    u64 r; asm("fma.rn.f32x2 %0, %1, %2, %3;" : "=l"(r) : "l"(a), "l"(b), "l"(c)); return r;
}
__device__ __forceinline__ float fast_ex2(float x) {
    float y; asm("ex2.approx.ftz.f32 %0, %1;" : "=f"(y) : "f"(x)); return y;
}
__device__ __forceinline__ float fast_rcp(float x) {
    float y; asm("rcp.approx.ftz.f32 %0, %1;" : "=f"(y) : "f"(x)); return y;
}

// ---------------------------------------------------------------------------
// Kernel 1: fold constants, one thread per GAUSSIAN PAIR. Odd-N tail lane is
// padded with c0=-1e30 (ex2 -> 0) and zero colors so it contributes nothing.
// ---------------------------------------------------------------------------
__global__ void prep_kernel(const float* __restrict__ positions,
                            const float* __restrict__ log_scales,
                            const float* __restrict__ colors,
                            const float* __restrict__ log_opacities,
                            int N) {
    int j = blockIdx.x * blockDim.x + threadIdx.x;
    int npairs = (N + 1) >> 1;
    if (j >= npairs) return;

    float npx[2], npy[2], a[2], b[2], c0[2], cr[2], cg[2], cb[2];
#pragma unroll
    for (int k = 0; k < 2; k++) {
        int i = 2 * j + k;
        if (i < N) {
            float sx = fmaxf(expf(log_scales[2 * i + 0]), MIN_SCALE);
            float sy = fmaxf(expf(log_scales[2 * i + 1]), MIN_SCALE);
            a[k]  = -0.5f * LOG2E_F / (sx * sx);
            b[k]  = -0.5f * LOG2E_F / (sy * sy);
            c0[k] = (log_opacities[i] - 1.8378770664093453f /*log(2pi)*/
                     - logf(sx) - logf(sy)) * LOG2E_F;
            npx[k] = -positions[2 * i + 0];
            npy[k] = -positions[2 * i + 1];
            cr[k] = colors[3 * i + 0];
            cg[k] = colors[3 * i + 1];
            cb[k] = colors[3 * i + 2];
        } else {                       // pad: alpha == 0 always
            a[k] = b[k] = -1.0f;
            c0[k] = -1e30f;
            npx[k] = npy[k] = 0.0f;
            cr[k] = cg[k] = cb[k] = 0.0f;
        }
    }

    g_tab[4 * j + 0] = make_ulonglong2(pack2(npx[0], npx[1]), pack2(npy[0], npy[1]));
    g_tab[4 * j + 1] = make_ulonglong2(pack2(a[0],   a[1]),   pack2(b[0],   b[1]));
    g_tab[4 * j + 2] = make_ulonglong2(pack2(c0[0],  c0[1]),  pack2(cr[0],  cr[1]));
    g_tab[4 * j + 3] = make_ulonglong2(pack2(cg[0],  cg[1]),  pack2(cb[0],  cb[1]));
}

// ---------------------------------------------------------------------------
// Kernel 2: render. 152 CTAs x 512 threads, 48KB static smem.
// ---------------------------------------------------------------------------
__global__ __launch_bounds__(BLOCK)
void render_kernel(const float* __restrict__ coords,
                   float* __restrict__ out,
                   int N, int P) {
    __shared__ ulonglong2 s_tab[4 * CPAIR];          // 16KB chunk of pair table
    __shared__ ulonglong2 s_acc[NSLOT][32][4];       // 32KB accumulator handoff

    const int tid  = threadIdx.x;
    const int wid  = tid >> 5;
    const int lane = tid & 31;
    const int b    = blockIdx.x;

    const int ntiles = (P + 63) >> 6;                // 64-pixel tiles
    const int npairs = (N + 1) >> 1;
    const int nchunk = (npairs + CPAIR - 1) / CPAIR;

    // packed accumulators: [pixel k] A,R,G,B ; lane0=even g, lane1=odd g
    u64 a0A = 0, a0R = 0, a0G = 0, a0B = 0;
    u64 a1A = 0, a1R = 0, a1G = 0, a1B = 0;
    u64 xx0 = 0, xx1 = 0, yy = 0;
    int  cur_s = 0, cur_t = 0;
    bool have = false;

    for (int c = 0; c < nchunk; c++) {
        // 1) hand off previous chunk's accumulators to the slot's next owner
        if (c > 0) {
            if (have) {
                s_acc[cur_s][lane][0] = make_ulonglong2(a0A, a0R);
                s_acc[cur_s][lane][1] = make_ulonglong2(a0G, a0B);
                s_acc[cur_s][lane][2] = make_ulonglong2(a1A, a1R);
                s_acc[cur_s][lane][3] = make_ulonglong2(a1G, a1B);
            }
            __syncthreads();
        }

        // 2) stage chunk c of the pair table
        const int pbase = c * CPAIR;
        const int cnt   = min(CPAIR, npairs - pbase);
        for (int i = tid; i < 4 * cnt; i += BLOCK) s_tab[i] = g_tab[4 * pbase + i];
        __syncthreads();

        // 3) rotate slot ownership: warp w takes slot (w+c)&15. Over 4 chunks
        //    SMSP k's warps {k,k+4,k+8,k+12} cover each slot exactly once ->
        //    per-SMSP units == active slots (7 or 6). Balanced.
        const int s = (wid + c) & (NSLOT - 1);
        const int t = b + s * gridDim.x;
        cur_s = s;
        cur_t = t;
        have  = (t < ntiles);
        if (!have) continue;

        // coords for this tile: one adjacent same-row pixel pair per lane
        const int pi = t * 32 + lane;
        const int p0 = 2 * pi;
        float4 c4;
        if (p0 + 1 < P) {
            c4 = ((const float4*)coords)[pi];
        } else if (p0 < P) {
            float2 c2 = ((const float2*)coords)[p0];
            c4 = make_float4(c2.x, c2.y, c2.x, c2.y);
        } else {
            c4 = make_float4(0.f, 0.f, 0.f, 0.f);
        }
        xx0 = pack2(c4.x, c4.x);          // {x0,x0}
        xx1 = pack2(c4.z, c4.z);          // {x1,x1}
        yy  = pack2(c4.y, c4.y);          // {y,y}  (p0 even => same row)

        // pick up accumulators from this slot's previous owner
        if (c == 0) {
            a0A = a0R = a0G = a0B = 0ull;
            a1A = a1R = a1G = a1B = 0ull;
        } else {
            ulonglong2 v0 = s_acc[s][lane][0];
            ulonglong2 v1 = s_acc[s][lane][1];
            ulonglong2 v2 = s_acc[s][lane][2];
            ulonglong2 v3 = s_acc[s][lane][3];
            a0A = v0.x; a0R = v0.y; a0G = v1.x; a0B = v1.y;
            a1A = v2.x; a1R = v2.y; a1G = v3.x; a1B = v3.y;
        }

        // ---- dual-stream depth-1 pipelined inner loop ---------------------
        // stream A: entries [0, half) ; stream B: entries [half, 2*half).
        // Carried per stream: exponents + colors of entry g (R12 pattern).
        const int half = cnt >> 1;

        u64 eA0, eA1, crA, cgA, cbA;       // stream A carried (entry 0)
        u64 eB0, eB1, crB, cgB, cbB;       // stream B carried (entry half)
        {
            const ulonglong2 w0 = s_tab[0];
            const ulonglong2 w1 = s_tab[1];
            const ulonglong2 w2 = s_tab[2];
            const ulonglong2 w3 = s_tab[3];
            u64 dy = f2add(yy, w0.y);
            u64 tt = f2fma(f2mul(dy, dy), w1.y, w2.x);
            u64 dx0 = f2add(xx0, w0.x);
            eA0 = f2fma(f2mul(dx0, dx0), w1.x, tt);
            u64 dx1 = f2add(xx1, w0.x);
            eA1 = f2fma(f2mul(dx1, dx1), w1.x, tt);
            crA = w2.y; cgA = w3.x; cbA = w3.y;

            const ulonglong2 u0 = s_tab[4 * half + 0];
            const ulonglong2 u1 = s_tab[4 * half + 1];
            const ulonglong2 u2 = s_tab[4 * half + 2];
            const ulonglong2 u3 = s_tab[4 * half + 3];
            u64 ey = f2add(yy, u0.y);
            u64 ts = f2fma(f2mul(ey, ey), u1.y, u2.x);
            u64 ex0 = f2add(xx0, u0.x);
            eB0 = f2fma(f2mul(ex0, ex0), u1.x, ts);
            u64 ex1 = f2add(xx1, u0.x);
            eB1 = f2fma(f2mul(ex1, ex1), u1.x, ts);
            crB = u2.y; cgB = u3.x; cbB = u3.y;
        }

#pragma unroll 2
        for (int g = 1; g < half; g++) {
            // launch MUFUs for both carried entries
            float f0, f1, f2, f3, h0, h1, h2, h3;
            unpack2(eA0, f0, f1);
            unpack2(eA1, f2, f3);
            unpack2(eB0, h0, h1);
            unpack2(eB1, h2, h3);
            const u64 alA0 = pack2(fast_ex2(f0), fast_ex2(f1));
            const u64 alA1 = pack2(fast_ex2(f2), fast_ex2(f3));
            const u64 alB0 = pack2(fast_ex2(h0), fast_ex2(h1));
            const u64 alB1 = pack2(fast_ex2(h2), fast_ex2(h3));

            // next entries for both streams (independent of the MUFUs)
            const ulonglong2 w0 = s_tab[4 * g + 0];
            const ulonglong2 w1 = s_tab[4 * g + 1];
            const ulonglong2 w2 = s_tab[4 * g + 2];
            const ulonglong2 w3 = s_tab[4 * g + 3];
            u64 dy = f2add(yy, w0.y);
            u64 tt = f2fma(f2mul(dy, dy), w1.y, w2.x);
            u64 dx0 = f2add(xx0, w0.x);
            u64 eA0n = f2fma(f2mul(dx0, dx0), w1.x, tt);
            u64 dx1 = f2add(xx1, w0.x);
            u64 eA1n = f2fma(f2mul(dx1, dx1), w1.x, tt);

            const ulonglong2 u0 = s_tab[4 * (half + g) + 0];
            const ulonglong2 u1 = s_tab[4 * (half + g) + 1];
            const ulonglong2 u2 = s_tab[4 * (half + g) + 2];
            const ulonglong2 u3 = s_tab[4 * (half + g) + 3];
            u64 ey = f2add(yy, u0.y);
            u64 ts = f2fma(f2mul(ey, ey), u1.y, u2.x);
            u64 ex0 = f2add(xx0, u0.x);
            u64 eB0n = f2fma(f2mul(ex0, ex0), u1.x, ts);
            u64 ex1 = f2add(xx1, u0.x);
            u64 eB1n = f2fma(f2mul(ex1, ex1), u1.x, ts);

            // accumulate both carried entries (A then B)
            a0A = f2add(a0A, alA0);
            a0R = f2fma(alA0, crA, a0R);
            a0G = f2fma(alA0, cgA, a0G);
            a0B = f2fma(alA0, cbA, a0B);
            a1A = f2add(a1A, alA1);
            a1R = f2fma(alA1, crA, a1R);
            a1G = f2fma(alA1, cgA, a1G);
            a1B = f2fma(alA1, cbA, a1B);

            a0A = f2add(a0A, alB0);
            a0R = f2fma(alB0, crB, a0R);
            a0G = f2fma(alB0, cgB, a0G);
            a0B = f2fma(alB0, cbB, a0B);
            a1A = f2add(a1A, alB1);
            a1R = f2fma(alB1, crB, a1R);
            a1G = f2fma(alB1, cgB, a1G);
            a1B = f2fma(alB1, cbB, a1B);

            // rotate carried state
            eA0 = eA0n; eA1 = eA1n; crA = w2.y; cgA = w3.x; cbA = w3.y;
            eB0 = eB0n; eB1 = eB1n; crB = u2.y; cgB = u3.x; cbB = u3.y;
        }

        // drain both carried entries (half-1 and 2*half-1)
        {
            float f0, f1, f2, f3, h0, h1, h2, h3;
            unpack2(eA0, f0, f1);
            unpack2(eA1, f2, f3);
            unpack2(eB0, h0, h1);
            unpack2(eB1, h2, h3);
            const u64 alA0 = pack2(fast_ex2(f0), fast_ex2(f1));
            const u64 alA1 = pack2(fast_ex2(f2), fast_ex2(f3));
            const u64 alB0 = pack2(fast_ex2(h0), fast_ex2(h1));
            const u64 alB1 = pack2(fast_ex2(h2), fast_ex2(h3));

            a0A = f2add(a0A, alA0);
            a0R = f2fma(alA0, crA, a0R);
            a0G = f2fma(alA0, cgA, a0G);
            a0B = f2fma(alA0, cbA, a0B);
            a1A = f2add(a1A, alA1);
            a1R = f2fma(alA1, crA, a1R);
            a1G = f2fma(alA1, cgA, a1G);
            a1B = f2fma(alA1, cbA, a1B);

            a0A = f2add(a0A, alB0);
            a0R = f2fma(alB0, crB, a0R);
            a0G = f2fma(alB0, cgB, a0G);
            a0B = f2fma(alB0, cbB, a0B);
            a1A = f2add(a1A, alB1);
            a1R = f2fma(alB1, crB, a1R);
            a1G = f2fma(alB1, cgB, a1G);
            a1B = f2fma(alB1, cbB, a1B);
        }

        // tail: odd cnt -> entry cnt-1 processed simply
        if (cnt & 1) {
            const int g = cnt - 1;
            const ulonglong2 w0 = s_tab[4 * g + 0];
            const ulonglong2 w1 = s_tab[4 * g + 1];
            const ulonglong2 w2 = s_tab[4 * g + 2];
            const ulonglong2 w3 = s_tab[4 * g + 3];
            u64 dy = f2add(yy, w0.y);
            u64 tt = f2fma(f2mul(dy, dy), w1.y, w2.x);
            u64 dx0 = f2add(xx0, w0.x);
            u64 e0 = f2fma(f2mul(dx0, dx0), w1.x, tt);
            u64 dx1 = f2add(xx1, w0.x);
            u64 e1 = f2fma(f2mul(dx1, dx1), w1.x, tt);
            float f0, f1, f2, f3;
            unpack2(e0, f0, f1);
            unpack2(e1, f2, f3);
            const u64 al0 = pack2(fast_ex2(f0), fast_ex2(f1));
            const u64 al1 = pack2(fast_ex2(f2), fast_ex2(f3));
            a0A = f2add(a0A, al0);
            a0R = f2fma(al0, w2.y, a0R);
            a0G = f2fma(al0, w3.x, a0G);
            a0B = f2fma(al0, w3.y, a0B);
            a1A = f2add(a1A, al1);
            a1R = f2fma(al1, w2.y, a1R);
            a1G = f2fma(al1, w3.x, a1G);
            a1B = f2fma(al1, w3.y, a1B);
        }
    }

    // Epilogue: finalize the tile owned in the LAST chunk (warp<->slot
    // bijection per chunk => every active tile written exactly once).
    if (have) {
        const int pi = cur_t * 32 + lane;
        const int p0 = 2 * pi;
        const int p1 = p0 + 1;

        float lo, hi;
        unpack2(a0A, lo, hi);  const float A0 = lo + hi;
        unpack2(a0R, lo, hi);  const float R0 = lo + hi;
        unpack2(a0G, lo, hi);  const float G0 = lo + hi;
        unpack2(a0B, lo, hi);  const float B0 = lo + hi;
        unpack2(a1A, lo, hi);  const float A1 = lo + hi;
        unpack2(a1R, lo, hi);  const float R1 = lo + hi;
        unpack2(a1G, lo, hi);  const float G1 = lo + hi;
        unpack2(a1B, lo, hi);  const float B1 = lo + hi;

        if (p1 < P) {
            const float i0 = fast_rcp(fmaxf(A0, MIN_ALPHA));
            const float i1 = fast_rcp(fmaxf(A1, MIN_ALPHA));
            float2* o = (float2*)(out + 3 * p0);   // 24B per pair, 8B-aligned
            o[0] = make_float2(__saturatef(R0 * i0), __saturatef(G0 * i0));
            o[1] = make_float2(__saturatef(B0 * i0), __saturatef(R1 * i1));
            o[2] = make_float2(__saturatef(G1 * i1), __saturatef(B1 * i1));
        } else if (p0 < P) {
            const float i0 = fast_rcp(fmaxf(A0, MIN_ALPHA));
            out[3 * p0 + 0] = __saturatef(R0 * i0);
            out[3 * p0 + 1] = __saturatef(G0 * i0);
            out[3 * p0 + 2] = __saturatef(B0 * i0);
        }
    }
}

// ---------------------------------------------------------------------------
// Launch
// ---------------------------------------------------------------------------
extern "C" void kernel_launch(void* const* d_in, const int* in_sizes, int n_in,
                              void* d_out, int out_size) {
    const float* coords        = (const float*)d_in[0];  // (P, 2)
    const float* positions     = (const float*)d_in[1];  // (N, 2)
    const float* log_scales    = (const float*)d_in[2];  // (N, 2)
    const float* colors        = (const float*)d_in[3];  // (N, 3)
    const float* log_opacities = (const float*)d_in[4];  // (N, 1)
    float*       out           = (float*)d_out;          // (P, 3)

    const int P = in_sizes[0] / 2;
    int N = in_sizes[1] / 2;
    if (N > NMAX) N = NMAX;

    const int npairs = (N + 1) >> 1;
    prep_kernel<<<(npairs + 255) / 256, 256>>>(positions, log_scales, colors,
                                               log_opacities, N);
    render_kernel<<<GRID, BLOCK>>>(coords, out, N, P);
}